// round 2
// baseline (speedup 1.0000x reference)
#include <cuda_runtime.h>

#define NN   4096
#define FIN  256
#define C1   512     // H1 * HID
#define H1   8
#define HID  64
#define OUT2 128
#define MAXN 512

// ---------------- scratch (no allocations allowed) ----------------
__device__ float g_h1[NN * C1];        // layer-1 features  [N, 512]
__device__ float g_hmid[NN * C1];      // layer-1 output    [N, 512]
__device__ float g_h2[NN * OUT2];      // layer-2 features  [N, 128]
__device__ float g_asrc1[NN * H1];
__device__ float g_adst1[NN * H1];
__device__ float g_asrc2[NN];
__device__ float g_adst2[NN];
__device__ unsigned short g_nbr[NN * MAXN];
__device__ int g_cnt[NN];

// ---------------- CSR build (deterministic, ordered) ----------------
__global__ void build_csr(const float* __restrict__ adj) {
    int row = blockIdx.x;
    int t   = threadIdx.x;                 // 256 threads
    const float* arow = adj + (size_t)row * NN;
    int base = t * 16;                     // 16 contiguous columns per thread

    float av[16];
    #pragma unroll
    for (int k = 0; k < 16; k++) av[k] = arow[base + k];

    int cnt = 0;
    #pragma unroll
    for (int k = 0; k < 16; k++) cnt += (av[k] != 0.0f);

    __shared__ int s[256];
    s[t] = cnt;
    __syncthreads();
    // inclusive Hillis-Steele scan
    for (int off = 1; off < 256; off <<= 1) {
        int v = (t >= off) ? s[t - off] : 0;
        __syncthreads();
        s[t] += v;
        __syncthreads();
    }
    int pos = s[t] - cnt;                  // exclusive prefix
    unsigned short* out = g_nbr + (size_t)row * MAXN;
    #pragma unroll
    for (int k = 0; k < 16; k++) {
        if (av[k] != 0.0f) {
            if (pos < MAXN) out[pos] = (unsigned short)(base + k);
            pos++;
        }
    }
    if (t == 255) g_cnt[row] = (s[255] < MAXN) ? s[255] : MAXN;
}

// ---------------- tiled fp32 GEMM: C = A[MxK] * B[KxN] ----------------
template <int BM, int BN, int BK, int TM, int TN>
__global__ void sgemm(const float* __restrict__ A, const float* __restrict__ B,
                      float* __restrict__ C, int M, int N, int K) {
    __shared__ float As[BK][BM];
    __shared__ float Bs[BK][BN];
    const int THREADS = (BM / TM) * (BN / TN);   // = 256 in both configs
    int tid = threadIdx.x;
    int tx  = tid % (BN / TN);
    int ty  = tid / (BN / TN);
    int m0  = blockIdx.y * BM;
    int n0  = blockIdx.x * BN;

    float acc[TM][TN];
    #pragma unroll
    for (int i = 0; i < TM; i++)
        #pragma unroll
        for (int j = 0; j < TN; j++) acc[i][j] = 0.0f;

    for (int k0 = 0; k0 < K; k0 += BK) {
        #pragma unroll
        for (int e = tid; e < BM * BK; e += THREADS) {
            int m = e / BK, k = e % BK;
            As[k][m] = A[(size_t)(m0 + m) * K + k0 + k];
        }
        #pragma unroll
        for (int e = tid; e < BK * BN; e += THREADS) {
            int k = e / BN, n = e % BN;
            Bs[k][n] = B[(size_t)(k0 + k) * N + n0 + n];
        }
        __syncthreads();
        #pragma unroll
        for (int kk = 0; kk < BK; kk++) {
            float a[TM], b[TN];
            #pragma unroll
            for (int i = 0; i < TM; i++) a[i] = As[kk][ty * TM + i];
            #pragma unroll
            for (int j = 0; j < TN; j++) b[j] = Bs[kk][tx * TN + j];
            #pragma unroll
            for (int i = 0; i < TM; i++)
                #pragma unroll
                for (int j = 0; j < TN; j++) acc[i][j] += a[i] * b[j];
        }
        __syncthreads();
    }
    #pragma unroll
    for (int i = 0; i < TM; i++)
        #pragma unroll
        for (int j = 0; j < TN; j++)
            C[(size_t)(m0 + ty * TM + i) * N + n0 + tx * TN + j] = acc[i][j];
}

// ---------------- attention scores, layer 1 ----------------
__global__ void scores1(const float* __restrict__ att_src,
                        const float* __restrict__ att_dst) {
    int n = blockIdx.x;
    int c = threadIdx.x;                  // 512
    __shared__ float ps[C1], pd[C1];
    float hv = g_h1[(size_t)n * C1 + c];
    ps[c] = hv * att_src[c];              // att flat [H1*HID] matches c layout
    pd[c] = hv * att_dst[c];
    __syncthreads();
    for (int off = 32; off >= 1; off >>= 1) {
        if ((c & 63) < off) { ps[c] += ps[c + off]; pd[c] += pd[c + off]; }
        __syncthreads();
    }
    if ((c & 63) == 0) {
        g_asrc1[n * H1 + (c >> 6)] = ps[c];
        g_adst1[n * H1 + (c >> 6)] = pd[c];
    }
}

// ---------------- attention scores, layer 2 ----------------
__global__ void scores2(const float* __restrict__ att_src,
                        const float* __restrict__ att_dst) {
    int n = blockIdx.x;
    int c = threadIdx.x;                  // 128
    __shared__ float ps[OUT2], pd[OUT2];
    float hv = g_h2[(size_t)n * OUT2 + c];
    ps[c] = hv * att_src[c];
    pd[c] = hv * att_dst[c];
    __syncthreads();
    for (int off = 64; off >= 1; off >>= 1) {
        if (c < off) { ps[c] += ps[c + off]; pd[c] += pd[c + off]; }
        __syncthreads();
    }
    if (c == 0) { g_asrc2[n] = ps[0]; g_adst2[n] = pd[0]; }
}

// ---------------- layer-1 sparse aggregation + bias + leaky(0.01) ----------------
__global__ void __launch_bounds__(512) agg1(const float* __restrict__ b1) {
    int i = blockIdx.x;
    int t = threadIdx.x;                  // 512
    __shared__ unsigned short s_nbr[MAXN];
    __shared__ float s_w[H1][MAXN];       // 16 KB
    __shared__ float s_part[H1 * 64];
    __shared__ float s_den[H1];

    int cnt = g_cnt[i];
    for (int jj = t; jj < cnt; jj += 512) s_nbr[jj] = g_nbr[(size_t)i * MAXN + jj];
    __syncthreads();

    // phase 1: edge weights exp(leaky_0.2(a_src[j,h] + a_dst[i,h]))
    float adst[H1];
    #pragma unroll
    for (int h = 0; h < H1; h++) adst[h] = g_adst1[i * H1 + h];
    for (int jj = t; jj < cnt; jj += 512) {
        int j = s_nbr[jj];
        #pragma unroll
        for (int h = 0; h < H1; h++) {
            float v = g_asrc1[j * H1 + h] + adst[h];
            v = v > 0.0f ? v : 0.2f * v;
            s_w[h][jj] = __expf(v);
        }
    }
    __syncthreads();

    // denominator per head
    {
        int h = t >> 6, k = t & 63;
        float s = 0.0f;
        for (int jj = k; jj < cnt; jj += 64) s += s_w[h][jj];
        s_part[t] = s;
        __syncthreads();
        for (int off = 32; off >= 1; off >>= 1) {
            if (k < off) s_part[t] += s_part[t + off];
            __syncthreads();
        }
        if (k == 0) s_den[h] = s_part[t];
        __syncthreads();
    }

    // phase 2: weighted gather over neighbors
    int c = t;
    int h = c >> 6;
    const float* wrow = s_w[h];
    float acc = 0.0f;
    int jj = 0;
    for (; jj + 4 <= cnt; jj += 4) {
        int j0 = s_nbr[jj], j1 = s_nbr[jj + 1], j2 = s_nbr[jj + 2], j3 = s_nbr[jj + 3];
        float v0 = g_h1[(size_t)j0 * C1 + c];
        float v1 = g_h1[(size_t)j1 * C1 + c];
        float v2 = g_h1[(size_t)j2 * C1 + c];
        float v3 = g_h1[(size_t)j3 * C1 + c];
        acc += wrow[jj] * v0;
        acc += wrow[jj + 1] * v1;
        acc += wrow[jj + 2] * v2;
        acc += wrow[jj + 3] * v3;
    }
    for (; jj < cnt; jj++) acc += wrow[jj] * g_h1[(size_t)s_nbr[jj] * C1 + c];

    float o = acc / s_den[h] + b1[c];
    o = o > 0.0f ? o : 0.01f * o;
    g_hmid[(size_t)i * C1 + c] = o;
}

// ---------------- layer-2 sparse aggregation + bias + leaky(0.01) ----------------
__global__ void __launch_bounds__(128) agg2(const float* __restrict__ b2,
                                            float* __restrict__ out) {
    int i = blockIdx.x;
    int t = threadIdx.x;                  // 128
    __shared__ unsigned short s_nbr[MAXN];
    __shared__ float s_w[MAXN];
    __shared__ float s_part[OUT2];
    __shared__ float s_den;

    int cnt = g_cnt[i];
    for (int jj = t; jj < cnt; jj += 128) s_nbr[jj] = g_nbr[(size_t)i * MAXN + jj];
    __syncthreads();

    float adst = g_adst2[i];
    for (int jj = t; jj < cnt; jj += 128) {
        float v = g_asrc2[s_nbr[jj]] + adst;
        v = v > 0.0f ? v : 0.2f * v;
        s_w[jj] = __expf(v);
    }
    __syncthreads();

    float s = 0.0f;
    for (int jj = t; jj < cnt; jj += 128) s += s_w[jj];
    s_part[t] = s;
    __syncthreads();
    for (int off = 64; off >= 1; off >>= 1) {
        if (t < off) s_part[t] += s_part[t + off];
        __syncthreads();
    }
    if (t == 0) s_den = s_part[0];
    __syncthreads();

    float acc = 0.0f;
    int jj = 0;
    for (; jj + 4 <= cnt; jj += 4) {
        int j0 = s_nbr[jj], j1 = s_nbr[jj + 1], j2 = s_nbr[jj + 2], j3 = s_nbr[jj + 3];
        float v0 = g_h2[(size_t)j0 * OUT2 + t];
        float v1 = g_h2[(size_t)j1 * OUT2 + t];
        float v2 = g_h2[(size_t)j2 * OUT2 + t];
        float v3 = g_h2[(size_t)j3 * OUT2 + t];
        acc += s_w[jj] * v0;
        acc += s_w[jj + 1] * v1;
        acc += s_w[jj + 2] * v2;
        acc += s_w[jj + 3] * v3;
    }
    for (; jj < cnt; jj++) acc += s_w[jj] * g_h2[(size_t)s_nbr[jj] * OUT2 + t];

    float o = acc / s_den + b2[t];
    o = o > 0.0f ? o : 0.01f * o;
    out[(size_t)i * OUT2 + t] = o;
}

// ---------------- launch ----------------
extern "C" void kernel_launch(void* const* d_in, const int* in_sizes, int n_in,
                              void* d_out, int out_size) {
    const float* x   = (const float*)d_in[0];
    const float* adj = (const float*)d_in[1];
    const float* w1  = (const float*)d_in[2];
    const float* as1 = (const float*)d_in[3];
    const float* ad1 = (const float*)d_in[4];
    const float* b1  = (const float*)d_in[5];
    const float* w2  = (const float*)d_in[6];
    const float* as2 = (const float*)d_in[7];
    const float* ad2 = (const float*)d_in[8];
    const float* b2  = (const float*)d_in[9];
    float* out = (float*)d_out;

    float *h1p, *hmidp, *h2p;
    cudaGetSymbolAddress((void**)&h1p,   g_h1);
    cudaGetSymbolAddress((void**)&hmidp, g_hmid);
    cudaGetSymbolAddress((void**)&h2p,   g_h2);

    build_csr<<<NN, 256>>>(adj);

    // h1 = x @ w1 : [4096,256] x [256,512]
    sgemm<128, 128, 8, 8, 8><<<dim3(C1 / 128, NN / 128), 256>>>(x, w1, h1p, NN, C1, FIN);

    scores1<<<NN, C1>>>(as1, ad1);
    agg1<<<NN, C1>>>(b1);

    // h2 = hmid @ w2 : [4096,512] x [512,128]
    sgemm<64, 64, 16, 4, 4><<<dim3(OUT2 / 64, NN / 64), 256>>>(hmidp, w2, h2p, NN, OUT2, C1);

    scores2<<<NN, OUT2>>>(as2, ad2);
    agg2<<<NN, OUT2>>>(b2, out);
}

// round 3
// speedup vs baseline: 1.6857x; 1.6857x over previous
#include <cuda_runtime.h>

#define NN   4096
#define FIN  256
#define C1   512     // H1 * HID
#define H1   8
#define HID  64
#define OUT2 128
#define MAXN 512
#define WPAD (MAXN + 4)   // padded s_w row stride (kills bank conflicts)

// ---------------- scratch (no allocations allowed) ----------------
__device__ float g_h1[NN * C1];        // layer-1 features  [N, 512]
__device__ float g_hmid[NN * C1];      // layer-1 output    [N, 512]
__device__ float g_h2[NN * OUT2];      // layer-2 features  [N, 128]
__device__ float g_asrc1[NN * H1];
__device__ float g_adst1[NN * H1];
__device__ float g_asrc2[NN];
__device__ float g_adst2[NN];
__device__ unsigned short g_nbr[NN * MAXN];
__device__ int g_cnt[NN];

// ---------------- CSR build (deterministic, ordered) ----------------
__global__ void build_csr(const float* __restrict__ adj) {
    int row = blockIdx.x;
    int t   = threadIdx.x;                 // 256 threads
    const float* arow = adj + (size_t)row * NN;
    int base = t * 16;                     // 16 contiguous columns per thread

    float av[16];
    #pragma unroll
    for (int q = 0; q < 4; q++) {
        float4 v = *(const float4*)(arow + base + q * 4);
        av[q * 4 + 0] = v.x; av[q * 4 + 1] = v.y;
        av[q * 4 + 2] = v.z; av[q * 4 + 3] = v.w;
    }

    int cnt = 0;
    #pragma unroll
    for (int k = 0; k < 16; k++) cnt += (av[k] != 0.0f);

    __shared__ int s[256];
    s[t] = cnt;
    __syncthreads();
    for (int off = 1; off < 256; off <<= 1) {
        int v = (t >= off) ? s[t - off] : 0;
        __syncthreads();
        s[t] += v;
        __syncthreads();
    }
    int pos = s[t] - cnt;                  // exclusive prefix
    unsigned short* out = g_nbr + (size_t)row * MAXN;
    #pragma unroll
    for (int k = 0; k < 16; k++) {
        if (av[k] != 0.0f) {
            if (pos < MAXN) out[pos] = (unsigned short)(base + k);
            pos++;
        }
    }
    if (t == 255) g_cnt[row] = (s[255] < MAXN) ? s[255] : MAXN;
}

// ---------------- tiled fp32 GEMM: C = A[MxK] * B[KxN], float4 I/O ----------------
template <int BM, int BN, int BK, int TM, int TN>
__global__ void sgemm(const float* __restrict__ A, const float* __restrict__ B,
                      float* __restrict__ C, int M, int N, int K) {
    __shared__ float As[BK][BM];
    __shared__ float Bs[BK][BN];
    const int THREADS = (BM / TM) * (BN / TN);   // 256 in both configs
    int tid = threadIdx.x;
    int tx  = tid % (BN / TN);
    int ty  = tid / (BN / TN);
    int m0  = blockIdx.y * BM;
    int n0  = blockIdx.x * BN;

    float acc[TM][TN];
    #pragma unroll
    for (int i = 0; i < TM; i++)
        #pragma unroll
        for (int j = 0; j < TN; j++) acc[i][j] = 0.0f;

    const int A4 = BM * BK / 4;
    const int B4 = BK * BN / 4;

    for (int k0 = 0; k0 < K; k0 += BK) {
        #pragma unroll
        for (int e = tid; e < A4; e += THREADS) {
            int m  = e / (BK / 4);
            int k4 = e % (BK / 4);
            float4 v = *(const float4*)&A[(size_t)(m0 + m) * K + k0 + k4 * 4];
            As[k4 * 4 + 0][m] = v.x;
            As[k4 * 4 + 1][m] = v.y;
            As[k4 * 4 + 2][m] = v.z;
            As[k4 * 4 + 3][m] = v.w;
        }
        #pragma unroll
        for (int e = tid; e < B4; e += THREADS) {
            int k  = e / (BN / 4);
            int n4 = e % (BN / 4);
            *(float4*)&Bs[k][n4 * 4] =
                *(const float4*)&B[(size_t)(k0 + k) * N + n0 + n4 * 4];
        }
        __syncthreads();
        #pragma unroll
        for (int kk = 0; kk < BK; kk++) {
            float a[TM], b[TN];
            #pragma unroll
            for (int i = 0; i < TM; i++) a[i] = As[kk][ty * TM + i];
            #pragma unroll
            for (int j = 0; j < TN; j++) b[j] = Bs[kk][tx * TN + j];
            #pragma unroll
            for (int i = 0; i < TM; i++)
                #pragma unroll
                for (int j = 0; j < TN; j++) acc[i][j] += a[i] * b[j];
        }
        __syncthreads();
    }
    #pragma unroll
    for (int i = 0; i < TM; i++)
        #pragma unroll
        for (int j4 = 0; j4 < TN / 4; j4++) {
            float4 v = make_float4(acc[i][j4 * 4 + 0], acc[i][j4 * 4 + 1],
                                   acc[i][j4 * 4 + 2], acc[i][j4 * 4 + 3]);
            *(float4*)&C[(size_t)(m0 + ty * TM + i) * N + n0 + tx * TN + j4 * 4] = v;
        }
}

// ---------------- attention scores, layer 1 ----------------
__global__ void scores1(const float* __restrict__ att_src,
                        const float* __restrict__ att_dst) {
    int n = blockIdx.x;
    int c = threadIdx.x;                  // 512
    __shared__ float ps[C1], pd[C1];
    float hv = g_h1[(size_t)n * C1 + c];
    ps[c] = hv * att_src[c];
    pd[c] = hv * att_dst[c];
    __syncthreads();
    for (int off = 32; off >= 1; off >>= 1) {
        if ((c & 63) < off) { ps[c] += ps[c + off]; pd[c] += pd[c + off]; }
        __syncthreads();
    }
    if ((c & 63) == 0) {
        g_asrc1[n * H1 + (c >> 6)] = ps[c];
        g_adst1[n * H1 + (c >> 6)] = pd[c];
    }
}

// ---------------- attention scores, layer 2 ----------------
__global__ void scores2(const float* __restrict__ att_src,
                        const float* __restrict__ att_dst) {
    int n = blockIdx.x;
    int c = threadIdx.x;                  // 128
    __shared__ float ps[OUT2], pd[OUT2];
    float hv = g_h2[(size_t)n * OUT2 + c];
    ps[c] = hv * att_src[c];
    pd[c] = hv * att_dst[c];
    __syncthreads();
    for (int off = 64; off >= 1; off >>= 1) {
        if (c < off) { ps[c] += ps[c + off]; pd[c] += pd[c + off]; }
        __syncthreads();
    }
    if (c == 0) { g_asrc2[n] = ps[0]; g_adst2[n] = pd[0]; }
}

// ---------------- layer-1 sparse aggregation (float4 gather) ----------------
__global__ void __launch_bounds__(512) agg1(const float* __restrict__ b1) {
    int i = blockIdx.x;
    int t = threadIdx.x;                  // 512
    __shared__ unsigned short s_nbr[MAXN];
    __shared__ float s_w[H1][WPAD];       // padded rows: no bank conflict
    __shared__ float s_part[H1 * 64];
    __shared__ float s_den[H1];
    __shared__ float4 s_red[4][128];      // cross-group partials

    int cnt = g_cnt[i];
    for (int jj = t; jj < cnt; jj += 512) s_nbr[jj] = g_nbr[(size_t)i * MAXN + jj];
    __syncthreads();

    // phase 1: edge weights exp(leaky_0.2(a_src[j,h] + a_dst[i,h]))
    float adst[H1];
    {
        float4 d0 = *(const float4*)&g_adst1[i * H1];
        float4 d1 = *(const float4*)&g_adst1[i * H1 + 4];
        adst[0] = d0.x; adst[1] = d0.y; adst[2] = d0.z; adst[3] = d0.w;
        adst[4] = d1.x; adst[5] = d1.y; adst[6] = d1.z; adst[7] = d1.w;
    }
    for (int jj = t; jj < cnt; jj += 512) {
        int j = s_nbr[jj];
        float4 a0 = *(const float4*)&g_asrc1[j * H1];
        float4 a1 = *(const float4*)&g_asrc1[j * H1 + 4];
        float av[H1] = {a0.x, a0.y, a0.z, a0.w, a1.x, a1.y, a1.z, a1.w};
        #pragma unroll
        for (int h = 0; h < H1; h++) {
            float v = av[h] + adst[h];
            v = v > 0.0f ? v : 0.2f * v;
            s_w[h][jj] = __expf(v);
        }
    }
    __syncthreads();

    // denominator per head
    {
        int h = t >> 6, k = t & 63;
        float s = 0.0f;
        for (int jj = k; jj < cnt; jj += 64) s += s_w[h][jj];
        s_part[t] = s;
        __syncthreads();
        for (int off = 32; off >= 1; off >>= 1) {
            if (k < off) s_part[t] += s_part[t + off];
            __syncthreads();
        }
        if (k == 0) s_den[h] = s_part[t];
        __syncthreads();
    }

    // phase 2: float4 gather. group g handles neighbors jj = g, g+4, ...
    {
        int g  = t >> 7;                  // 0..3
        int c4 = t & 127;                 // float4 lane: channels [c4*4, c4*4+4)
        int h  = c4 >> 4;                 // head for these 4 channels
        const float* wrow = s_w[h];
        const float4* hbase = (const float4*)g_h1;
        float4 acc = make_float4(0.f, 0.f, 0.f, 0.f);
        for (int jj = g; jj < cnt; jj += 4) {
            int j = s_nbr[jj];
            float4 v = hbase[(size_t)j * (C1 / 4) + c4];
            float w = wrow[jj];
            acc.x += w * v.x; acc.y += w * v.y;
            acc.z += w * v.z; acc.w += w * v.w;
        }
        s_red[g][c4] = acc;
        __syncthreads();

        if (t < 128) {
            float4 a0 = s_red[0][t], a1 = s_red[1][t], a2 = s_red[2][t], a3 = s_red[3][t];
            float inv = 1.0f / s_den[t >> 4];
            float4 bb = *(const float4*)&b1[t * 4];
            float4 o;
            o.x = (a0.x + a1.x + a2.x + a3.x) * inv + bb.x;
            o.y = (a0.y + a1.y + a2.y + a3.y) * inv + bb.y;
            o.z = (a0.z + a1.z + a2.z + a3.z) * inv + bb.z;
            o.w = (a0.w + a1.w + a2.w + a3.w) * inv + bb.w;
            o.x = o.x > 0.f ? o.x : 0.01f * o.x;
            o.y = o.y > 0.f ? o.y : 0.01f * o.y;
            o.z = o.z > 0.f ? o.z : 0.01f * o.z;
            o.w = o.w > 0.f ? o.w : 0.01f * o.w;
            ((float4*)g_hmid)[(size_t)i * (C1 / 4) + t] = o;
        }
    }
}

// ---------------- layer-2 sparse aggregation (float4 gather) ----------------
__global__ void __launch_bounds__(128) agg2(const float* __restrict__ b2,
                                            float* __restrict__ out) {
    int i = blockIdx.x;
    int t = threadIdx.x;                  // 128
    __shared__ unsigned short s_nbr[MAXN];
    __shared__ float s_w[MAXN];
    __shared__ float s_part[OUT2];
    __shared__ float s_den;
    __shared__ float4 s_red[4][32];

    int cnt = g_cnt[i];
    for (int jj = t; jj < cnt; jj += 128) s_nbr[jj] = g_nbr[(size_t)i * MAXN + jj];
    __syncthreads();

    float adst = g_adst2[i];
    for (int jj = t; jj < cnt; jj += 128) {
        float v = g_asrc2[s_nbr[jj]] + adst;
        v = v > 0.0f ? v : 0.2f * v;
        s_w[jj] = __expf(v);
    }
    __syncthreads();

    float s = 0.0f;
    for (int jj = t; jj < cnt; jj += 128) s += s_w[jj];
    s_part[t] = s;
    __syncthreads();
    for (int off = 64; off >= 1; off >>= 1) {
        if (t < off) s_part[t] += s_part[t + off];
        __syncthreads();
    }
    if (t == 0) s_den = s_part[0];
    __syncthreads();

    // float4 gather: group g = t>>5 (one warp), lane c4 = t&31
    {
        int g  = t >> 5;
        int c4 = t & 31;
        const float4* hbase = (const float4*)g_h2;
        float4 acc = make_float4(0.f, 0.f, 0.f, 0.f);
        for (int jj = g; jj < cnt; jj += 4) {
            int j = s_nbr[jj];
            float4 v = hbase[(size_t)j * (OUT2 / 4) + c4];
            float w = s_w[jj];
            acc.x += w * v.x; acc.y += w * v.y;
            acc.z += w * v.z; acc.w += w * v.w;
        }
        s_red[g][c4] = acc;
        __syncthreads();

        if (t < 32) {
            float4 a0 = s_red[0][t], a1 = s_red[1][t], a2 = s_red[2][t], a3 = s_red[3][t];
            float inv = 1.0f / s_den;
            float4 bb = *(const float4*)&b2[t * 4];
            float4 o;
            o.x = (a0.x + a1.x + a2.x + a3.x) * inv + bb.x;
            o.y = (a0.y + a1.y + a2.y + a3.y) * inv + bb.y;
            o.z = (a0.z + a1.z + a2.z + a3.z) * inv + bb.z;
            o.w = (a0.w + a1.w + a2.w + a3.w) * inv + bb.w;
            o.x = o.x > 0.f ? o.x : 0.01f * o.x;
            o.y = o.y > 0.f ? o.y : 0.01f * o.y;
            o.z = o.z > 0.f ? o.z : 0.01f * o.z;
            o.w = o.w > 0.f ? o.w : 0.01f * o.w;
            ((float4*)out)[(size_t)i * (OUT2 / 4) + t] = o;
        }
    }
}

// ---------------- launch ----------------
extern "C" void kernel_launch(void* const* d_in, const int* in_sizes, int n_in,
                              void* d_out, int out_size) {
    const float* x   = (const float*)d_in[0];
    const float* adj = (const float*)d_in[1];
    const float* w1  = (const float*)d_in[2];
    const float* as1 = (const float*)d_in[3];
    const float* ad1 = (const float*)d_in[4];
    const float* b1  = (const float*)d_in[5];
    const float* w2  = (const float*)d_in[6];
    const float* as2 = (const float*)d_in[7];
    const float* ad2 = (const float*)d_in[8];
    const float* b2  = (const float*)d_in[9];
    float* out = (float*)d_out;

    float *h1p, *hmidp, *h2p;
    cudaGetSymbolAddress((void**)&h1p,   g_h1);
    cudaGetSymbolAddress((void**)&hmidp, g_hmid);
    cudaGetSymbolAddress((void**)&h2p,   g_h2);

    build_csr<<<NN, 256>>>(adj);

    // h1 = x @ w1 : [4096,256] x [256,512]
    sgemm<128, 128, 8, 8, 8><<<dim3(C1 / 128, NN / 128), 256>>>(x, w1, h1p, NN, C1, FIN);

    scores1<<<NN, C1>>>(as1, ad1);
    agg1<<<NN, C1>>>(b1);

    // h2 = hmid @ w2 : [4096,512] x [512,128]
    sgemm<64, 64, 16, 4, 4><<<dim3(OUT2 / 64, NN / 64), 256>>>(hmidp, w2, h2p, NN, OUT2, C1);

    scores2<<<NN, OUT2>>>(as2, ad2);
    agg2<<<NN, OUT2>>>(b2, out);
}

// round 4
// speedup vs baseline: 1.8482x; 1.0964x over previous
#include <cuda_runtime.h>
#include <cuda_bf16.h>

#define NN   4096
#define FIN  256
#define C1   512     // H1 * HID
#define H1   8
#define HID  64
#define OUT2 128
#define MAXN 512
#define WPAD (MAXN + 4)

// ---------------- scratch (no allocations allowed) ----------------
__device__ float g_h1[NN * C1];          // layer-1 features fp32 (for scores)
__device__ uint4 g_h1b[NN * C1 / 8];     // layer-1 features bf16 (for gather)
__device__ float g_hmid[NN * C1];        // layer-1 output fp32
__device__ float g_h2[NN * OUT2];        // layer-2 features fp32 (for scores)
__device__ uint4 g_h2b[NN * OUT2 / 8];   // layer-2 features bf16 (for gather)
__device__ float g_asrc1[NN * H1];
__device__ float g_adst1[NN * H1];
__device__ float g_asrc2[NN];
__device__ float g_adst2[NN];
__device__ unsigned short g_nbr[NN * MAXN];
__device__ int g_cnt[NN];

__device__ __forceinline__ float bflo(unsigned u) { return __uint_as_float(u << 16); }
__device__ __forceinline__ float bfhi(unsigned u) { return __uint_as_float(u & 0xffff0000u); }

// ---------------- CSR build (deterministic, ordered) ----------------
__global__ void build_csr(const float* __restrict__ adj) {
    int row = blockIdx.x;
    int t   = threadIdx.x;                 // 256
    const float* arow = adj + (size_t)row * NN;
    int base = t * 16;

    float av[16];
    #pragma unroll
    for (int q = 0; q < 4; q++) {
        float4 v = *(const float4*)(arow + base + q * 4);
        av[q * 4 + 0] = v.x; av[q * 4 + 1] = v.y;
        av[q * 4 + 2] = v.z; av[q * 4 + 3] = v.w;
    }
    int cnt = 0;
    #pragma unroll
    for (int k = 0; k < 16; k++) cnt += (av[k] != 0.0f);

    __shared__ int s[256];
    s[t] = cnt;
    __syncthreads();
    for (int off = 1; off < 256; off <<= 1) {
        int v = (t >= off) ? s[t - off] : 0;
        __syncthreads();
        s[t] += v;
        __syncthreads();
    }
    int pos = s[t] - cnt;
    unsigned short* out = g_nbr + (size_t)row * MAXN;
    #pragma unroll
    for (int k = 0; k < 16; k++) {
        if (av[k] != 0.0f) {
            if (pos < MAXN) out[pos] = (unsigned short)(base + k);
            pos++;
        }
    }
    if (t == 255) g_cnt[row] = (s[255] < MAXN) ? s[255] : MAXN;
}

// ------ tiled fp32 GEMM: C = A[MxK]*B[KxN]; optional bf16 secondary output ------
template <int BM, int BN, int BK, int TM, int TN>
__global__ void sgemm(const float* __restrict__ A, const float* __restrict__ B,
                      float* __restrict__ C, __nv_bfloat162* __restrict__ Cb,
                      int M, int N, int K) {
    __shared__ float As[BK][BM];
    __shared__ float Bs[BK][BN];
    const int THREADS = (BM / TM) * (BN / TN);   // 256
    int tid = threadIdx.x;
    int tx  = tid % (BN / TN);
    int ty  = tid / (BN / TN);
    int m0  = blockIdx.y * BM;
    int n0  = blockIdx.x * BN;

    float acc[TM][TN];
    #pragma unroll
    for (int i = 0; i < TM; i++)
        #pragma unroll
        for (int j = 0; j < TN; j++) acc[i][j] = 0.0f;

    const int A4 = BM * BK / 4;
    const int B4 = BK * BN / 4;

    for (int k0 = 0; k0 < K; k0 += BK) {
        #pragma unroll
        for (int e = tid; e < A4; e += THREADS) {
            int m  = e / (BK / 4);
            int k4 = e % (BK / 4);
            float4 v = *(const float4*)&A[(size_t)(m0 + m) * K + k0 + k4 * 4];
            As[k4 * 4 + 0][m] = v.x;
            As[k4 * 4 + 1][m] = v.y;
            As[k4 * 4 + 2][m] = v.z;
            As[k4 * 4 + 3][m] = v.w;
        }
        #pragma unroll
        for (int e = tid; e < B4; e += THREADS) {
            int k  = e / (BN / 4);
            int n4 = e % (BN / 4);
            *(float4*)&Bs[k][n4 * 4] =
                *(const float4*)&B[(size_t)(k0 + k) * N + n0 + n4 * 4];
        }
        __syncthreads();
        #pragma unroll
        for (int kk = 0; kk < BK; kk++) {
            float a[TM], b[TN];
            #pragma unroll
            for (int i = 0; i < TM; i++) a[i] = As[kk][ty * TM + i];
            #pragma unroll
            for (int j = 0; j < TN; j++) b[j] = Bs[kk][tx * TN + j];
            #pragma unroll
            for (int i = 0; i < TM; i++)
                #pragma unroll
                for (int j = 0; j < TN; j++) acc[i][j] += a[i] * b[j];
        }
        __syncthreads();
    }
    #pragma unroll
    for (int i = 0; i < TM; i++) {
        size_t roff = (size_t)(m0 + ty * TM + i) * N + n0 + tx * TN;
        #pragma unroll
        for (int j4 = 0; j4 < TN / 4; j4++) {
            float4 v = make_float4(acc[i][j4 * 4 + 0], acc[i][j4 * 4 + 1],
                                   acc[i][j4 * 4 + 2], acc[i][j4 * 4 + 3]);
            *(float4*)&C[roff + j4 * 4] = v;
        }
        if (Cb) {
            #pragma unroll
            for (int j2 = 0; j2 < TN / 2; j2++)
                Cb[(roff >> 1) + j2] =
                    __floats2bfloat162_rn(acc[i][j2 * 2], acc[i][j2 * 2 + 1]);
        }
    }
}

// ---------------- attention scores, layer 1 ----------------
__global__ void scores1(const float* __restrict__ att_src,
                        const float* __restrict__ att_dst) {
    int n = blockIdx.x;
    int c = threadIdx.x;                  // 512
    __shared__ float ps[C1], pd[C1];
    float hv = g_h1[(size_t)n * C1 + c];
    ps[c] = hv * att_src[c];
    pd[c] = hv * att_dst[c];
    __syncthreads();
    for (int off = 32; off >= 1; off >>= 1) {
        if ((c & 63) < off) { ps[c] += ps[c + off]; pd[c] += pd[c + off]; }
        __syncthreads();
    }
    if ((c & 63) == 0) {
        g_asrc1[n * H1 + (c >> 6)] = ps[c];
        g_adst1[n * H1 + (c >> 6)] = pd[c];
    }
}

// ---------------- attention scores, layer 2 ----------------
__global__ void scores2(const float* __restrict__ att_src,
                        const float* __restrict__ att_dst) {
    int n = blockIdx.x;
    int c = threadIdx.x;                  // 128
    __shared__ float ps[OUT2], pd[OUT2];
    float hv = g_h2[(size_t)n * OUT2 + c];
    ps[c] = hv * att_src[c];
    pd[c] = hv * att_dst[c];
    __syncthreads();
    for (int off = 64; off >= 1; off >>= 1) {
        if (c < off) { ps[c] += ps[c + off]; pd[c] += pd[c + off]; }
        __syncthreads();
    }
    if (c == 0) { g_asrc2[n] = ps[0]; g_adst2[n] = pd[0]; }
}

// ---------------- layer-1 sparse aggregation (bf16 uint4 gather) ----------------
__global__ void __launch_bounds__(512) agg1(const float* __restrict__ b1) {
    int i = blockIdx.x;
    int t = threadIdx.x;                  // 512
    __shared__ unsigned short s_nbr[MAXN];
    __shared__ float s_w[H1][WPAD];
    __shared__ float s_part[H1 * 64];
    __shared__ float s_den[H1];
    __shared__ float s_red[8][8][64];     // [group][k][c8] 16KB, conflict-free

    int cnt = g_cnt[i];
    for (int jj = t; jj < cnt; jj += 512) s_nbr[jj] = g_nbr[(size_t)i * MAXN + jj];
    __syncthreads();

    // phase 1: edge weights
    float adst[H1];
    {
        float4 d0 = *(const float4*)&g_adst1[i * H1];
        float4 d1 = *(const float4*)&g_adst1[i * H1 + 4];
        adst[0] = d0.x; adst[1] = d0.y; adst[2] = d0.z; adst[3] = d0.w;
        adst[4] = d1.x; adst[5] = d1.y; adst[6] = d1.z; adst[7] = d1.w;
    }
    for (int jj = t; jj < cnt; jj += 512) {
        int j = s_nbr[jj];
        float4 a0 = *(const float4*)&g_asrc1[j * H1];
        float4 a1 = *(const float4*)&g_asrc1[j * H1 + 4];
        float av[H1] = {a0.x, a0.y, a0.z, a0.w, a1.x, a1.y, a1.z, a1.w};
        #pragma unroll
        for (int h = 0; h < H1; h++) {
            float v = av[h] + adst[h];
            v = v > 0.0f ? v : 0.2f * v;
            s_w[h][jj] = __expf(v);
        }
    }
    __syncthreads();

    // denominator per head
    {
        int h = t >> 6, k = t & 63;
        float s = 0.0f;
        for (int jj = k; jj < cnt; jj += 64) s += s_w[h][jj];
        s_part[t] = s;
        __syncthreads();
        for (int off = 32; off >= 1; off >>= 1) {
            if (k < off) s_part[t] += s_part[t + off];
            __syncthreads();
        }
        if (k == 0) s_den[h] = s_part[t];
        __syncthreads();
    }

    // phase 2: bf16 gather. lane c8 covers channels [c8*8, c8*8+8); 8 edge groups
    {
        int c8 = t & 63;
        int g  = t >> 6;                  // 0..7
        int h  = c8 >> 3;
        const float* wrow = s_w[h];
        float acc[8] = {0, 0, 0, 0, 0, 0, 0, 0};
        for (int jj = g; jj < cnt; jj += 8) {
            int j = s_nbr[jj];
            uint4 v = g_h1b[(size_t)j * (C1 / 8) + c8];
            float w = wrow[jj];
            acc[0] += w * bflo(v.x); acc[1] += w * bfhi(v.x);
            acc[2] += w * bflo(v.y); acc[3] += w * bfhi(v.y);
            acc[4] += w * bflo(v.z); acc[5] += w * bfhi(v.z);
            acc[6] += w * bflo(v.w); acc[7] += w * bfhi(v.w);
        }
        #pragma unroll
        for (int k = 0; k < 8; k++) s_red[g][k][c8] = acc[k];
        __syncthreads();

        if (t < 64) {
            float inv = 1.0f / s_den[t >> 3];
            float o[8];
            #pragma unroll
            for (int k = 0; k < 8; k++) {
                float s = 0.0f;
                #pragma unroll
                for (int gg = 0; gg < 8; gg++) s += s_red[gg][k][t];
                float v = s * inv + b1[t * 8 + k];
                o[k] = v > 0.0f ? v : 0.01f * v;
            }
            float4* dst = (float4*)&g_hmid[(size_t)i * C1 + t * 8];
            dst[0] = make_float4(o[0], o[1], o[2], o[3]);
            dst[1] = make_float4(o[4], o[5], o[6], o[7]);
        }
    }
}

// ---------------- layer-2 sparse aggregation (bf16 uint4 gather) ----------------
__global__ void __launch_bounds__(128) agg2(const float* __restrict__ b2,
                                            float* __restrict__ out) {
    int i = blockIdx.x;
    int t = threadIdx.x;                  // 128
    __shared__ unsigned short s_nbr[MAXN];
    __shared__ float s_w[MAXN];
    __shared__ float s_part[OUT2];
    __shared__ float s_den;
    __shared__ float s_red[8][8][16];     // [group][k][c8] 4KB

    int cnt = g_cnt[i];
    for (int jj = t; jj < cnt; jj += 128) s_nbr[jj] = g_nbr[(size_t)i * MAXN + jj];
    __syncthreads();

    float adst = g_adst2[i];
    for (int jj = t; jj < cnt; jj += 128) {
        float v = g_asrc2[s_nbr[jj]] + adst;
        v = v > 0.0f ? v : 0.2f * v;
        s_w[jj] = __expf(v);
    }
    __syncthreads();

    float s = 0.0f;
    for (int jj = t; jj < cnt; jj += 128) s += s_w[jj];
    s_part[t] = s;
    __syncthreads();
    for (int off = 64; off >= 1; off >>= 1) {
        if (t < off) s_part[t] += s_part[t + off];
        __syncthreads();
    }
    if (t == 0) s_den = s_part[0];
    __syncthreads();

    // bf16 gather: lane c8 covers channels [c8*8, c8*8+8); 8 edge groups
    {
        int c8 = t & 15;
        int g  = t >> 4;                  // 0..7
        float acc[8] = {0, 0, 0, 0, 0, 0, 0, 0};
        for (int jj = g; jj < cnt; jj += 8) {
            int j = s_nbr[jj];
            uint4 v = g_h2b[(size_t)j * (OUT2 / 8) + c8];
            float w = s_w[jj];
            acc[0] += w * bflo(v.x); acc[1] += w * bfhi(v.x);
            acc[2] += w * bflo(v.y); acc[3] += w * bfhi(v.y);
            acc[4] += w * bflo(v.z); acc[5] += w * bfhi(v.z);
            acc[6] += w * bflo(v.w); acc[7] += w * bfhi(v.w);
        }
        #pragma unroll
        for (int k = 0; k < 8; k++) s_red[g][k][c8] = acc[k];
        __syncthreads();

        if (t < 16) {
            float inv = 1.0f / s_den;
            float o[8];
            #pragma unroll
            for (int k = 0; k < 8; k++) {
                float ss = 0.0f;
                #pragma unroll
                for (int gg = 0; gg < 8; gg++) ss += s_red[gg][k][t];
                float v = ss * inv + b2[t * 8 + k];
                o[k] = v > 0.0f ? v : 0.01f * v;
            }
            float4* dst = (float4*)&out[(size_t)i * OUT2 + t * 8];
            dst[0] = make_float4(o[0], o[1], o[2], o[3]);
            dst[1] = make_float4(o[4], o[5], o[6], o[7]);
        }
    }
}

// ---------------- launch ----------------
extern "C" void kernel_launch(void* const* d_in, const int* in_sizes, int n_in,
                              void* d_out, int out_size) {
    const float* x   = (const float*)d_in[0];
    const float* adj = (const float*)d_in[1];
    const float* w1  = (const float*)d_in[2];
    const float* as1 = (const float*)d_in[3];
    const float* ad1 = (const float*)d_in[4];
    const float* b1  = (const float*)d_in[5];
    const float* w2  = (const float*)d_in[6];
    const float* as2 = (const float*)d_in[7];
    const float* ad2 = (const float*)d_in[8];
    const float* b2  = (const float*)d_in[9];
    float* out = (float*)d_out;

    float *h1p, *hmidp, *h2p;
    __nv_bfloat162 *h1bp, *h2bp;
    cudaGetSymbolAddress((void**)&h1p,   g_h1);
    cudaGetSymbolAddress((void**)&hmidp, g_hmid);
    cudaGetSymbolAddress((void**)&h2p,   g_h2);
    cudaGetSymbolAddress((void**)&h1bp,  g_h1b);
    cudaGetSymbolAddress((void**)&h2bp,  g_h2b);

    build_csr<<<NN, 256>>>(adj);

    // h1 = x @ w1 : [4096,256] x [256,512]  (+ bf16 copy)
    sgemm<128, 128, 8, 8, 8><<<dim3(C1 / 128, NN / 128), 256>>>(
        x, w1, h1p, h1bp, NN, C1, FIN);

    scores1<<<NN, C1>>>(as1, ad1);
    agg1<<<NN, C1>>>(b1);

    // h2 = hmid @ w2 : [4096,512] x [512,128]  (+ bf16 copy)
    sgemm<64, 64, 16, 4, 4><<<dim3(OUT2 / 64, NN / 64), 256>>>(
        hmidp, w2, h2p, h2bp, NN, OUT2, C1);

    scores2<<<NN, OUT2>>>(as2, ad2);
    agg2<<<NN, OUT2>>>(b2, out);
}